// round 1
// baseline (speedup 1.0000x reference)
#include <cuda_runtime.h>
#include <math.h>

// Problem constants
#define B_SZ     4
#define SEQ_LEN  2048
#define D_MODEL  256
#define D_INNER  512
#define D_STATE  16
#define KCONV    4
#define DT_RANK  16
#define N_CLS    10
#define BL       (B_SZ * SEQ_LEN)          // 8192
#define XPROJ_N  (DT_RANK + 2 * D_STATE)   // 48

// Scratch (device globals; no allocation allowed)
__device__ float g_xz[BL * 2 * D_INNER];     // (8192, 1024) : u | z
__device__ float g_uc[BL * D_INNER];         // (8192, 512)
__device__ float g_xdbl[BL * XPROJ_N];       // (8192, 48)  : dt_raw | Bp | Cp
__device__ float g_dt[BL * D_INNER];         // (8192, 512)
__device__ float g_pooled[B_SZ * D_INNER];   // (4, 512)

// ---------------------------------------------------------------------------
// K1: xz = x @ W_in      (8192 x 1024, K=256)  classic tiled SGEMM 128x128x8
// ---------------------------------------------------------------------------
__global__ __launch_bounds__(256) void gemm1_kernel(const float* __restrict__ A,
                                                    const float* __restrict__ Bm) {
    constexpr int N = 2 * D_INNER, K = D_MODEL;
    constexpr int BM = 128, BN = 128, BK = 8, TM = 8, TN = 8;
    __shared__ float As[BK][BM];
    __shared__ float Bs[BK][BN];
    const int tid = threadIdx.x;
    const float* Ab = A + blockIdx.y * BM * K;
    const float* Bb = Bm + blockIdx.x * BN;
    float* Cb = g_xz + blockIdx.y * BM * N + blockIdx.x * BN;

    const int arow = tid >> 1, acol = (tid & 1) << 2;   // A: 128 rows x 8 cols
    const int brow = tid >> 5, bcol = (tid & 31) << 2;  // B: 8 rows x 128 cols
    const int ty = tid >> 4, tx = tid & 15;

    float acc[TM][TN] = {};
    for (int k0 = 0; k0 < K; k0 += BK) {
        float4 a4 = *(const float4*)(Ab + arow * K + k0 + acol);
        As[acol + 0][arow] = a4.x;
        As[acol + 1][arow] = a4.y;
        As[acol + 2][arow] = a4.z;
        As[acol + 3][arow] = a4.w;
        *(float4*)(&Bs[brow][bcol]) = *(const float4*)(Bb + (k0 + brow) * N + bcol);
        __syncthreads();
#pragma unroll
        for (int kk = 0; kk < BK; kk++) {
            float ra[TM], rb[TN];
#pragma unroll
            for (int i = 0; i < TM; i += 4)
                *(float4*)(ra + i) = *(const float4*)(&As[kk][ty * TM + i]);
#pragma unroll
            for (int j = 0; j < TN; j += 4)
                *(float4*)(rb + j) = *(const float4*)(&Bs[kk][tx * TN + j]);
#pragma unroll
            for (int i = 0; i < TM; i++)
#pragma unroll
                for (int j = 0; j < TN; j++)
                    acc[i][j] = fmaf(ra[i], rb[j], acc[i][j]);
        }
        __syncthreads();
    }
#pragma unroll
    for (int i = 0; i < TM; i++)
#pragma unroll
        for (int j = 0; j < TN; j += 4) {
            float4 v = make_float4(acc[i][j], acc[i][j + 1], acc[i][j + 2], acc[i][j + 3]);
            *(float4*)(Cb + (ty * TM + i) * N + tx * TN + j) = v;
        }
}

// ---------------------------------------------------------------------------
// K2: depthwise causal conv (K=4) + bias + SiLU -> u_c
// ---------------------------------------------------------------------------
__global__ __launch_bounds__(256) void conv_kernel(const float* __restrict__ W_conv,
                                                   const float* __restrict__ b_conv) {
    const int idx = blockIdx.x * 256 + threadIdx.x;        // over 8192*512
    const int d  = idx & (D_INNER - 1);
    const int bl = idx >> 9;
    const int l  = bl & (SEQ_LEN - 1);
    const int b  = bl >> 11;
    float acc = b_conv[d];
#pragma unroll
    for (int k = 0; k < KCONV; k++) {
        const int ll = l + k - (KCONV - 1);
        if (ll >= 0)
            acc = fmaf(g_xz[(size_t)(b * SEQ_LEN + ll) * (2 * D_INNER) + d],
                       W_conv[d * KCONV + k], acc);
    }
    g_uc[idx] = acc / (1.0f + expf(-acc));  // silu
}

// ---------------------------------------------------------------------------
// K3: x_dbl = u_c @ W_xproj    (8192 x 48, K=512); 16 rows per block
// ---------------------------------------------------------------------------
__global__ __launch_bounds__(256) void xproj_kernel(const float* __restrict__ W_xproj) {
    constexpr int ROWS = 16, KC = 128;                 // K chunk
    __shared__ float u_s[ROWS][KC];
    __shared__ float W_s[KC * XPROJ_N];                // 24 KB
    const int tid = threadIdx.x;
    const int row0 = blockIdx.x * ROWS;
    // per-thread outputs: o = s*256 + tid, s = 0..2  (16*48 = 768 outputs)
    int r[3], j[3];
    float acc[3] = {0.f, 0.f, 0.f};
#pragma unroll
    for (int s = 0; s < 3; s++) { int o = s * 256 + tid; r[s] = o / XPROJ_N; j[s] = o % XPROJ_N; }

    for (int k0 = 0; k0 < D_INNER; k0 += KC) {
        __syncthreads();
        for (int i = tid; i < ROWS * KC; i += 256) {
            int rr = i >> 7, kk = i & (KC - 1);
            u_s[rr][kk] = g_uc[(size_t)(row0 + rr) * D_INNER + k0 + kk];
        }
        for (int i = tid; i < KC * XPROJ_N; i += 256)
            W_s[i] = W_xproj[(size_t)k0 * XPROJ_N + i];
        __syncthreads();
#pragma unroll 4
        for (int kk = 0; kk < KC; kk++) {
#pragma unroll
            for (int s = 0; s < 3; s++)
                acc[s] = fmaf(u_s[r[s]][kk], W_s[kk * XPROJ_N + j[s]], acc[s]);
        }
    }
#pragma unroll
    for (int s = 0; s < 3; s++)
        g_xdbl[(size_t)(row0 + r[s]) * XPROJ_N + j[s]] = acc[s];
}

// ---------------------------------------------------------------------------
// K4: dt = softplus(dt_raw @ W_dt + b_dt)   (8192 x 512, K=16)
// ---------------------------------------------------------------------------
__global__ __launch_bounds__(256) void dt_kernel(const float* __restrict__ W_dt,
                                                 const float* __restrict__ b_dt) {
    const int idx = blockIdx.x * 256 + threadIdx.x;    // over 8192*512
    const int d  = idx & (D_INNER - 1);
    const int bl = idx >> 9;
    float acc = b_dt[d];
    const float* xr = g_xdbl + (size_t)bl * XPROJ_N;
#pragma unroll
    for (int r = 0; r < DT_RANK; r++)
        acc = fmaf(xr[r], W_dt[r * D_INNER + d], acc);
    // softplus (stable)
    g_dt[idx] = (acc > 20.0f) ? acc : log1pf(expf(acc));
}

// ---------------------------------------------------------------------------
// K5: selective scan, fused gating + D-skip + pooling accumulation.
// Block: 16 (b,d) groups x 16 state lanes = 256 threads. 128 blocks total.
// Stages 32-timestep chunks into SMEM; serial dep is only the h FMA chain.
// ---------------------------------------------------------------------------
__global__ __launch_bounds__(256) void scan_kernel(const float* __restrict__ A_log,
                                                   const float* __restrict__ Dp) {
    constexpr int CH = 32;  // timesteps per chunk
    __shared__ float dt_s[CH][16];
    __shared__ float u_s[CH][16];
    __shared__ float z_s[CH][16];
    __shared__ float xd_s[CH * XPROJ_N];
    const int tid = threadIdx.x;
    const int gi = tid >> 4;       // group within block (d offset)
    const int n  = tid & 15;       // state index
    const int g0 = blockIdx.x * 16;
    const int b  = g0 >> 9;
    const int d0 = g0 & (D_INNER - 1);
    const int d  = d0 + gi;

    const float A_n = -__expf(A_log[d * D_STATE + n]);
    const float Dd  = Dp[d];

    float h = 0.f, acc = 0.f, accD = 0.f;
    for (int l0 = 0; l0 < SEQ_LEN; l0 += CH) {
        __syncthreads();
        const size_t bl0 = (size_t)(b * SEQ_LEN + l0);
        for (int i = tid; i < CH * 16; i += 256) {
            int li = i >> 4, dd = i & 15;
            size_t bl = bl0 + li;
            dt_s[li][dd] = g_dt[bl * D_INNER + d0 + dd];
            u_s[li][dd]  = g_uc[bl * D_INNER + d0 + dd];
            z_s[li][dd]  = g_xz[bl * (2 * D_INNER) + D_INNER + d0 + dd];
        }
        for (int i = tid; i < CH * XPROJ_N; i += 256)
            xd_s[i] = g_xdbl[bl0 * XPROJ_N + i];
        __syncthreads();
#pragma unroll 8
        for (int li = 0; li < CH; li++) {
            const float w  = dt_s[li][gi];
            const float u  = u_s[li][gi];
            const float zv = z_s[li][gi];
            const float bn = xd_s[li * XPROJ_N + DT_RANK + n];
            const float cn = xd_s[li * XPROJ_N + DT_RANK + D_STATE + n];
            const float dA = __expf(w * A_n);
            h = fmaf(dA, h, w * bn * u);
            const float gate = zv * __frcp_rn(1.0f + __expf(-zv));  // z*sigmoid(z)
            acc  = fmaf(gate * cn, h, acc);
            accD = fmaf(gate, u, accD);
        }
    }
    // reduce acc over the 16 state lanes (one time, end of sequence)
#pragma unroll
    for (int off = 8; off >= 1; off >>= 1)
        acc += __shfl_xor_sync(0xffffffffu, acc, off);
    if (n == 0)
        g_pooled[b * D_INNER + d] = (acc + Dd * accD) * (1.0f / SEQ_LEN);
}

// ---------------------------------------------------------------------------
// K6: logits = (pooled @ W_out) @ W_cls + b_cls   (tiny: 4x512 -> 4x256 -> 4x10)
// ---------------------------------------------------------------------------
__global__ __launch_bounds__(256) void final_kernel(const float* __restrict__ W_out,
                                                    const float* __restrict__ W_cls,
                                                    const float* __restrict__ b_cls,
                                                    float* __restrict__ out) {
    __shared__ float p_s[B_SZ * D_INNER];   // 8 KB
    __shared__ float t_s[B_SZ * D_MODEL];   // 4 KB
    const int tid = threadIdx.x;
    for (int i = tid; i < B_SZ * D_INNER; i += 256) p_s[i] = g_pooled[i];
    __syncthreads();
    float a0 = 0.f, a1 = 0.f, a2 = 0.f, a3 = 0.f;
    for (int k = 0; k < D_INNER; k++) {
        const float w = W_out[k * D_MODEL + tid];
        a0 = fmaf(p_s[k], w, a0);
        a1 = fmaf(p_s[D_INNER + k], w, a1);
        a2 = fmaf(p_s[2 * D_INNER + k], w, a2);
        a3 = fmaf(p_s[3 * D_INNER + k], w, a3);
    }
    t_s[tid] = a0; t_s[D_MODEL + tid] = a1;
    t_s[2 * D_MODEL + tid] = a2; t_s[3 * D_MODEL + tid] = a3;
    __syncthreads();
    if (tid < B_SZ * N_CLS) {
        const int bb = tid / N_CLS, c = tid % N_CLS;
        float acc = b_cls[c];
        for (int k = 0; k < D_MODEL; k++)
            acc = fmaf(t_s[bb * D_MODEL + k], W_cls[k * N_CLS + c], acc);
        out[tid] = acc;
    }
}

// ---------------------------------------------------------------------------
extern "C" void kernel_launch(void* const* d_in, const int* in_sizes, int n_in,
                              void* d_out, int out_size) {
    const float* x       = (const float*)d_in[0];
    const float* W_in    = (const float*)d_in[1];
    const float* W_conv  = (const float*)d_in[2];
    const float* b_conv  = (const float*)d_in[3];
    const float* W_xproj = (const float*)d_in[4];
    const float* W_dt    = (const float*)d_in[5];
    const float* b_dt    = (const float*)d_in[6];
    const float* A_log   = (const float*)d_in[7];
    const float* Dp      = (const float*)d_in[8];
    const float* W_out   = (const float*)d_in[9];
    const float* W_cls   = (const float*)d_in[10];
    const float* b_cls   = (const float*)d_in[11];
    float* out = (float*)d_out;

    gemm1_kernel<<<dim3(2 * D_INNER / 128, BL / 128), 256>>>(x, W_in);
    conv_kernel<<<BL * D_INNER / 256, 256>>>(W_conv, b_conv);
    xproj_kernel<<<BL / 16, 256>>>(W_xproj);
    dt_kernel<<<BL * D_INNER / 256, 256>>>(W_dt, b_dt);
    scan_kernel<<<B_SZ * D_INNER / 16, 256>>>(A_log, Dp);
    final_kernel<<<1, 256>>>(W_out, W_cls, b_cls, out);
}

// round 2
// speedup vs baseline: 2.1258x; 2.1258x over previous
#include <cuda_runtime.h>
#include <math.h>

// Problem constants
#define B_SZ     4
#define SEQ_LEN  2048
#define D_MODEL  256
#define D_INNER  512
#define D_STATE  16
#define KCONV    4
#define DT_RANK  16
#define N_CLS    10
#define BL       (B_SZ * SEQ_LEN)          // 8192
#define XPROJ_N  (DT_RANK + 2 * D_STATE)   // 48

// Scratch (device globals; no allocation allowed)
__device__ float g_xz[BL * 2 * D_INNER];     // (8192, 1024) : u | z
__device__ float g_uc[BL * D_INNER];         // (8192, 512)
__device__ float g_xdbl[BL * XPROJ_N];       // (8192, 48)  : dt_raw | Bp | Cp
__device__ float g_pooled[B_SZ * D_INNER];   // (4, 512)

// ---------------------------------------------------------------------------
// K1: xz = x @ W_in  (8192 x 1024, K=256)
// Double-buffered 128x128x16 SGEMM, 1 sync per K-chunk, 8x8 per-thread tile.
// ---------------------------------------------------------------------------
__global__ __launch_bounds__(256) void gemm1_kernel(const float* __restrict__ A,
                                                    const float* __restrict__ Bm) {
    constexpr int N = 2 * D_INNER, K = D_MODEL;
    constexpr int BM = 128, BN = 128, BK = 16, TM = 8, TN = 8;
    constexpr int NCHUNK = K / BK;  // 16
    __shared__ float As[2][BK][BM + 4];
    __shared__ float Bs[2][BK][BN];
    const int tid = threadIdx.x;
    const float* Ab = A + blockIdx.y * BM * K;
    const float* Bb = Bm + blockIdx.x * BN;
    float* Cb = g_xz + blockIdx.y * BM * N + blockIdx.x * BN;

    // A tile: 128 rows x 16 cols = 512 float4, 2 per thread
    const int a_row0 = tid >> 2, a_c4 = (tid & 3) << 2;       // +64 rows for i=1
    // B tile: 16 rows x 128 cols = 512 float4, 2 per thread
    const int b_row0 = tid >> 5, b_col = (tid & 31) << 2;     // +8 rows for i=1
    const int ty = tid >> 4, tx = tid & 15;

    float acc[TM][TN] = {};
    float4 pa[2], pb[2];

    // prologue: chunk 0 -> buffer 0
    pa[0] = *(const float4*)(Ab + a_row0 * K + a_c4);
    pa[1] = *(const float4*)(Ab + (a_row0 + 64) * K + a_c4);
    pb[0] = *(const float4*)(Bb + b_row0 * N + b_col);
    pb[1] = *(const float4*)(Bb + (b_row0 + 8) * N + b_col);
#pragma unroll
    for (int i = 0; i < 2; i++) {
        const int r = a_row0 + i * 64;
        As[0][a_c4 + 0][r] = pa[i].x; As[0][a_c4 + 1][r] = pa[i].y;
        As[0][a_c4 + 2][r] = pa[i].z; As[0][a_c4 + 3][r] = pa[i].w;
        *(float4*)(&Bs[0][b_row0 + i * 8][b_col]) = pb[i];
    }
    __syncthreads();

    int buf = 0;
    for (int c = 0; c < NCHUNK; c++) {
        if (c + 1 < NCHUNK) {
            const int k0 = (c + 1) * BK;
            pa[0] = *(const float4*)(Ab + a_row0 * K + k0 + a_c4);
            pa[1] = *(const float4*)(Ab + (a_row0 + 64) * K + k0 + a_c4);
            pb[0] = *(const float4*)(Bb + (k0 + b_row0) * N + b_col);
            pb[1] = *(const float4*)(Bb + (k0 + b_row0 + 8) * N + b_col);
        }
#pragma unroll
        for (int kk = 0; kk < BK; kk++) {
            float ra[TM], rb[TN];
#pragma unroll
            for (int i = 0; i < TM; i += 4)
                *(float4*)(ra + i) = *(const float4*)(&As[buf][kk][ty * TM + i]);
#pragma unroll
            for (int j = 0; j < TN; j += 4)
                *(float4*)(rb + j) = *(const float4*)(&Bs[buf][kk][tx * TN + j]);
#pragma unroll
            for (int i = 0; i < TM; i++)
#pragma unroll
                for (int j = 0; j < TN; j++)
                    acc[i][j] = fmaf(ra[i], rb[j], acc[i][j]);
        }
        if (c + 1 < NCHUNK) {
            const int nb = buf ^ 1;
#pragma unroll
            for (int i = 0; i < 2; i++) {
                const int r = a_row0 + i * 64;
                As[nb][a_c4 + 0][r] = pa[i].x; As[nb][a_c4 + 1][r] = pa[i].y;
                As[nb][a_c4 + 2][r] = pa[i].z; As[nb][a_c4 + 3][r] = pa[i].w;
                *(float4*)(&Bs[nb][b_row0 + i * 8][b_col]) = pb[i];
            }
            __syncthreads();
            buf ^= 1;
        }
    }
#pragma unroll
    for (int i = 0; i < TM; i++)
#pragma unroll
        for (int j = 0; j < TN; j += 4) {
            float4 v = make_float4(acc[i][j], acc[i][j + 1], acc[i][j + 2], acc[i][j + 3]);
            *(float4*)(Cb + (ty * TM + i) * N + tx * TN + j) = v;
        }
}

// ---------------------------------------------------------------------------
// K2: depthwise causal conv (K=4) + bias + SiLU -> u_c
// ---------------------------------------------------------------------------
__global__ __launch_bounds__(256) void conv_kernel(const float* __restrict__ W_conv,
                                                   const float* __restrict__ b_conv) {
    const int idx = blockIdx.x * 256 + threadIdx.x;        // over 8192*512
    const int d  = idx & (D_INNER - 1);
    const int bl = idx >> 9;
    const int l  = bl & (SEQ_LEN - 1);
    const int b  = bl >> 11;
    float acc = b_conv[d];
#pragma unroll
    for (int k = 0; k < KCONV; k++) {
        const int ll = l + k - (KCONV - 1);
        if (ll >= 0)
            acc = fmaf(g_xz[(size_t)(b * SEQ_LEN + ll) * (2 * D_INNER) + d],
                       W_conv[d * KCONV + k], acc);
    }
    g_uc[idx] = acc * __frcp_rn(1.0f + __expf(-acc));  // silu
}

// ---------------------------------------------------------------------------
// K3: x_dbl = u_c @ W_xproj    (8192 x 48, K=512); 16 rows per block.
// Threads 0..191 compute: j = tid%48, 4 rows each (broadcast SMEM reads).
// ---------------------------------------------------------------------------
__global__ __launch_bounds__(256) void xproj_kernel(const float* __restrict__ W_xproj) {
    constexpr int ROWS = 16, KC = 64;
    __shared__ float u_s[ROWS][KC];        // 4 KB
    __shared__ float W_s[KC][XPROJ_N];     // 12 KB
    const int tid = threadIdx.x;
    const int row0 = blockIdx.x * ROWS;
    const int j  = tid % XPROJ_N;
    const int rq = (tid / XPROJ_N) * 4;    // 0,4,8,12 for tid<192
    const bool active = tid < 192;

    float acc[4] = {0.f, 0.f, 0.f, 0.f};
    for (int k0 = 0; k0 < D_INNER; k0 += KC) {
        __syncthreads();
        for (int i = tid; i < ROWS * KC; i += 256) {
            const int rr = i >> 6, kk = i & (KC - 1);
            u_s[rr][kk] = g_uc[(size_t)(row0 + rr) * D_INNER + k0 + kk];
        }
        for (int i = tid; i < KC * XPROJ_N; i += 256)
            W_s[i / XPROJ_N][i % XPROJ_N] = W_xproj[(size_t)k0 * XPROJ_N + i];
        __syncthreads();
        if (active) {
#pragma unroll 8
            for (int kk = 0; kk < KC; kk++) {
                const float w = W_s[kk][j];
                acc[0] = fmaf(u_s[rq + 0][kk], w, acc[0]);
                acc[1] = fmaf(u_s[rq + 1][kk], w, acc[1]);
                acc[2] = fmaf(u_s[rq + 2][kk], w, acc[2]);
                acc[3] = fmaf(u_s[rq + 3][kk], w, acc[3]);
            }
        }
    }
    if (active) {
#pragma unroll
        for (int i = 0; i < 4; i++)
            g_xdbl[(size_t)(row0 + rq + i) * XPROJ_N + j] = acc[i];
    }
}

// ---------------------------------------------------------------------------
// K4: selective scan with fused dt-projection/softplus, gating, D-skip and
// pooling accumulation. Block: 16 d-channels x 16 state lanes = 256 threads.
// Per 32-step chunk: phase1 coop load, phase2 dt/gate precompute (all
// n-independent math hoisted out of the serial loop), phase3 serial scan.
// ---------------------------------------------------------------------------
__global__ __launch_bounds__(256) void scan_kernel(const float* __restrict__ A_log,
                                                   const float* __restrict__ Dp,
                                                   const float* __restrict__ W_dt,
                                                   const float* __restrict__ b_dt) {
    constexpr int CH = 32;   // timesteps per chunk
    constexpr int PW = 36;   // padded row (16B-aligned, conflict-light)
    __shared__ float w_s[16][PW];     // dt            [dd][li]
    __shared__ float wu_s[16][PW];    // dt*u  (phase1: u)
    __shared__ float g_s[16][PW];     // gate  (phase1: z)
    __shared__ float xd_s[CH * XPROJ_N];
    __shared__ float Wdt_s[DT_RANK][16];
    __shared__ float bdt_s[16];
    __shared__ float accD_red[16][16];

    const int tid = threadIdx.x;
    const int gi = tid >> 4;       // d channel within block
    const int n  = tid & 15;       // state index
    const int g0 = blockIdx.x * 16;
    const int b  = g0 >> 9;
    const int d0 = g0 & (D_INNER - 1);
    const int d  = d0 + gi;

    // phase2 mapping (fixed per thread): dd = tid&15, li in {tid>>4, tid>>4 + 16}
    const int p_dd = tid & 15;
    const int p_li = tid >> 4;

    if (tid < DT_RANK * 16)
        Wdt_s[tid >> 4][tid & 15] = W_dt[(tid >> 4) * D_INNER + d0 + (tid & 15)];
    if (tid < 16) bdt_s[tid] = b_dt[d0 + tid];

    const float A_n = -__expf(A_log[d * D_STATE + n]);
    const float Dd  = Dp[d];

    float h = 0.f, acc = 0.f, accD_th = 0.f;

    for (int l0 = 0; l0 < SEQ_LEN; l0 += CH) {
        __syncthreads();   // WAR: previous chunk's phase3 done
        const size_t bl0 = (size_t)(b * SEQ_LEN + l0);
        // ---- phase 1: cooperative loads (coalesced) ----
        {
            const int dd = tid & 15, li0 = tid >> 4;   // 2 rows per thread
#pragma unroll
            for (int s = 0; s < 2; s++) {
                const int li = li0 + s * 16;
                const size_t bl = bl0 + li;
                wu_s[dd][li] = g_uc[bl * D_INNER + d0 + dd];                      // u
                g_s[dd][li]  = g_xz[bl * (2 * D_INNER) + D_INNER + d0 + dd];      // z
            }
        }
#pragma unroll
        for (int s = 0; s < 6; s++) {
            const int i = tid + s * 256;
            if (i < CH * XPROJ_N) xd_s[i] = g_xdbl[bl0 * XPROJ_N + i];
        }
        __syncthreads();
        // ---- phase 2: dt = softplus(xd . W_dt + b), gate = silu(z) ----
#pragma unroll
        for (int s = 0; s < 2; s++) {
            const int li = p_li + s * 16;
            float dtr = bdt_s[p_dd];
#pragma unroll
            for (int r = 0; r < DT_RANK; r++)
                dtr = fmaf(xd_s[li * XPROJ_N + r], Wdt_s[r][p_dd], dtr);
            const float w = (dtr > 15.0f) ? dtr : log1pf(__expf(dtr));
            const float u = wu_s[p_dd][li];
            const float z = g_s[p_dd][li];
            const float gate = z * __frcp_rn(1.0f + __expf(-z));
            w_s[p_dd][li]  = w;
            wu_s[p_dd][li] = w * u;
            g_s[p_dd][li]  = gate;
            accD_th = fmaf(gate, u, accD_th);
        }
        __syncthreads();
        // ---- phase 3: serial scan over the chunk ----
#pragma unroll
        for (int l4 = 0; l4 < CH; l4 += 4) {
            const float4 w4  = *(const float4*)&w_s[gi][l4];
            const float4 wu4 = *(const float4*)&wu_s[gi][l4];
            const float4 g4  = *(const float4*)&g_s[gi][l4];
            const float* xb = xd_s + l4 * XPROJ_N + DT_RANK + n;
#pragma unroll
            for (int q = 0; q < 4; q++) {
                const float w  = (q == 0) ? w4.x  : (q == 1) ? w4.y  : (q == 2) ? w4.z  : w4.w;
                const float wu = (q == 0) ? wu4.x : (q == 1) ? wu4.y : (q == 2) ? wu4.z : wu4.w;
                const float gt = (q == 0) ? g4.x  : (q == 1) ? g4.y  : (q == 2) ? g4.z  : g4.w;
                const float bn = xb[q * XPROJ_N];
                const float cn = xb[q * XPROJ_N + D_STATE];
                const float dA = __expf(w * A_n);
                h = fmaf(dA, h, wu * bn);
                acc = fmaf(gt * cn, h, acc);
            }
        }
    }
    // reduce acc over the 16 state lanes
#pragma unroll
    for (int off = 8; off >= 1; off >>= 1)
        acc += __shfl_xor_sync(0xffffffffu, acc, off);
    // reduce accD (per dd across the 16 phase2-threads that share it)
    accD_red[tid >> 4][p_dd] = accD_th;
    __syncthreads();
    if (n == 0) {
        float accD = 0.f;
#pragma unroll
        for (int g = 0; g < 16; g++) accD += accD_red[g][gi];
        g_pooled[b * D_INNER + d] = (acc + Dd * accD) * (1.0f / SEQ_LEN);
    }
}

// ---------------------------------------------------------------------------
// K5: logits = (pooled @ W_out) @ W_cls + b_cls   (tiny)
// ---------------------------------------------------------------------------
__global__ __launch_bounds__(256) void final_kernel(const float* __restrict__ W_out,
                                                    const float* __restrict__ W_cls,
                                                    const float* __restrict__ b_cls,
                                                    float* __restrict__ out) {
    __shared__ float p_s[B_SZ * D_INNER];
    __shared__ float t_s[B_SZ * D_MODEL];
    const int tid = threadIdx.x;
    for (int i = tid; i < B_SZ * D_INNER; i += 256) p_s[i] = g_pooled[i];
    __syncthreads();
    float a0 = 0.f, a1 = 0.f, a2 = 0.f, a3 = 0.f;
    for (int k = 0; k < D_INNER; k++) {
        const float w = W_out[k * D_MODEL + tid];
        a0 = fmaf(p_s[k], w, a0);
        a1 = fmaf(p_s[D_INNER + k], w, a1);
        a2 = fmaf(p_s[2 * D_INNER + k], w, a2);
        a3 = fmaf(p_s[3 * D_INNER + k], w, a3);
    }
    t_s[tid] = a0; t_s[D_MODEL + tid] = a1;
    t_s[2 * D_MODEL + tid] = a2; t_s[3 * D_MODEL + tid] = a3;
    __syncthreads();
    if (tid < B_SZ * N_CLS) {
        const int bb = tid / N_CLS, c = tid % N_CLS;
        float acc = b_cls[c];
        for (int k = 0; k < D_MODEL; k++)
            acc = fmaf(t_s[bb * D_MODEL + k], W_cls[k * N_CLS + c], acc);
        out[tid] = acc;
    }
}

// ---------------------------------------------------------------------------
extern "C" void kernel_launch(void* const* d_in, const int* in_sizes, int n_in,
                              void* d_out, int out_size) {
    const float* x       = (const float*)d_in[0];
    const float* W_in    = (const float*)d_in[1];
    const float* W_conv  = (const float*)d_in[2];
    const float* b_conv  = (const float*)d_in[3];
    const float* W_xproj = (const float*)d_in[4];
    const float* W_dt    = (const float*)d_in[5];
    const float* b_dt    = (const float*)d_in[6];
    const float* A_log   = (const float*)d_in[7];
    const float* Dp      = (const float*)d_in[8];
    const float* W_out   = (const float*)d_in[9];
    const float* W_cls   = (const float*)d_in[10];
    const float* b_cls   = (const float*)d_in[11];
    float* out = (float*)d_out;

    gemm1_kernel<<<dim3(2 * D_INNER / 128, BL / 128), 256>>>(x, W_in);
    conv_kernel<<<BL * D_INNER / 256, 256>>>(W_conv, b_conv);
    xproj_kernel<<<BL / 16, 256>>>(W_xproj);
    scan_kernel<<<B_SZ * D_INNER / 16, 256>>>(A_log, Dp, W_dt, b_dt);
    final_kernel<<<1, 256>>>(W_out, W_cls, b_cls, out);
}

// round 5
// speedup vs baseline: 2.2200x; 1.0443x over previous
#include <cuda_runtime.h>
#include <math.h>

// Problem constants
#define B_SZ     4
#define SEQ_LEN  2048
#define D_MODEL  256
#define D_INNER  512
#define D_STATE  16
#define KCONV    4
#define DT_RANK  16
#define N_CLS    10
#define BL       (B_SZ * SEQ_LEN)          // 8192
#define XPROJ_N  (DT_RANK + 2 * D_STATE)   // 48
#define SEGS     16
#define SEG_LEN  (SEQ_LEN / SEGS)          // 128

// Scratch (device globals; no allocation allowed)
__device__ float g_xz[BL * 2 * D_INNER];     // (8192, 1024) : u | z
__device__ float g_uc[BL * D_INNER];         // (8192, 512)
__device__ float g_xdbl[BL * XPROJ_N];       // (8192, 48)  : dt_raw | Bp | Cp
__device__ float g_pooled[B_SZ * D_INNER];   // (4, 512)
// Segment-scan summaries, packed: [b][seg][d][n] -> {locAcc, coef, Aprod, hend}
__device__ float4 g_seg[B_SZ * SEGS * D_INNER * D_STATE];
__device__ float  g_accD[B_SZ * SEGS * D_INNER];

// ---------------------------------------------------------------------------
// K1: xz = x @ W_in  (8192 x 1024, K=256)
// Double-buffered 128x128x16 SGEMM, 1 sync per K-chunk, 8x8 per-thread tile.
// ---------------------------------------------------------------------------
__global__ __launch_bounds__(256) void gemm1_kernel(const float* __restrict__ A,
                                                    const float* __restrict__ Bm) {
    constexpr int N = 2 * D_INNER, K = D_MODEL;
    constexpr int BM = 128, BN = 128, BK = 16, TM = 8, TN = 8;
    constexpr int NCHUNK = K / BK;  // 16
    __shared__ float As[2][BK][BM + 4];
    __shared__ float Bs[2][BK][BN];
    const int tid = threadIdx.x;
    const float* Ab = A + blockIdx.y * BM * K;
    const float* Bb = Bm + blockIdx.x * BN;
    float* Cb = g_xz + blockIdx.y * BM * N + blockIdx.x * BN;

    const int a_row0 = tid >> 2, a_c4 = (tid & 3) << 2;
    const int b_row0 = tid >> 5, b_col = (tid & 31) << 2;
    const int ty = tid >> 4, tx = tid & 15;

    float acc[TM][TN] = {};
    float4 pa[2], pb[2];

    pa[0] = *(const float4*)(Ab + a_row0 * K + a_c4);
    pa[1] = *(const float4*)(Ab + (a_row0 + 64) * K + a_c4);
    pb[0] = *(const float4*)(Bb + b_row0 * N + b_col);
    pb[1] = *(const float4*)(Bb + (b_row0 + 8) * N + b_col);
#pragma unroll
    for (int i = 0; i < 2; i++) {
        const int r = a_row0 + i * 64;
        As[0][a_c4 + 0][r] = pa[i].x; As[0][a_c4 + 1][r] = pa[i].y;
        As[0][a_c4 + 2][r] = pa[i].z; As[0][a_c4 + 3][r] = pa[i].w;
        *(float4*)(&Bs[0][b_row0 + i * 8][b_col]) = pb[i];
    }
    __syncthreads();

    int buf = 0;
    for (int c = 0; c < NCHUNK; c++) {
        if (c + 1 < NCHUNK) {
            const int k0 = (c + 1) * BK;
            pa[0] = *(const float4*)(Ab + a_row0 * K + k0 + a_c4);
            pa[1] = *(const float4*)(Ab + (a_row0 + 64) * K + k0 + a_c4);
            pb[0] = *(const float4*)(Bb + (k0 + b_row0) * N + b_col);
            pb[1] = *(const float4*)(Bb + (k0 + b_row0 + 8) * N + b_col);
        }
#pragma unroll
        for (int kk = 0; kk < BK; kk++) {
            float ra[TM], rb[TN];
#pragma unroll
            for (int i = 0; i < TM; i += 4)
                *(float4*)(ra + i) = *(const float4*)(&As[buf][kk][ty * TM + i]);
#pragma unroll
            for (int j = 0; j < TN; j += 4)
                *(float4*)(rb + j) = *(const float4*)(&Bs[buf][kk][tx * TN + j]);
#pragma unroll
            for (int i = 0; i < TM; i++)
#pragma unroll
                for (int j = 0; j < TN; j++)
                    acc[i][j] = fmaf(ra[i], rb[j], acc[i][j]);
        }
        if (c + 1 < NCHUNK) {
            const int nb = buf ^ 1;
#pragma unroll
            for (int i = 0; i < 2; i++) {
                const int r = a_row0 + i * 64;
                As[nb][a_c4 + 0][r] = pa[i].x; As[nb][a_c4 + 1][r] = pa[i].y;
                As[nb][a_c4 + 2][r] = pa[i].z; As[nb][a_c4 + 3][r] = pa[i].w;
                *(float4*)(&Bs[nb][b_row0 + i * 8][b_col]) = pb[i];
            }
            __syncthreads();
            buf ^= 1;
        }
    }
#pragma unroll
    for (int i = 0; i < TM; i++)
#pragma unroll
        for (int j = 0; j < TN; j += 4) {
            float4 v = make_float4(acc[i][j], acc[i][j + 1], acc[i][j + 2], acc[i][j + 3]);
            *(float4*)(Cb + (ty * TM + i) * N + tx * TN + j) = v;
        }
}

// ---------------------------------------------------------------------------
// K2: depthwise causal conv (K=4) + bias + SiLU -> u_c
// ---------------------------------------------------------------------------
__global__ __launch_bounds__(256) void conv_kernel(const float* __restrict__ W_conv,
                                                   const float* __restrict__ b_conv) {
    const int idx = blockIdx.x * 256 + threadIdx.x;        // over 8192*512
    const int d  = idx & (D_INNER - 1);
    const int bl = idx >> 9;
    const int l  = bl & (SEQ_LEN - 1);
    const int b  = bl >> 11;
    float acc = b_conv[d];
#pragma unroll
    for (int k = 0; k < KCONV; k++) {
        const int ll = l + k - (KCONV - 1);
        if (ll >= 0)
            acc = fmaf(g_xz[(size_t)(b * SEQ_LEN + ll) * (2 * D_INNER) + d],
                       W_conv[d * KCONV + k], acc);
    }
    g_uc[idx] = acc * __frcp_rn(1.0f + __expf(-acc));  // silu
}

// ---------------------------------------------------------------------------
// K3: x_dbl = u_c @ W_xproj    (8192 x 48, K=512); 16 rows per block.
// ---------------------------------------------------------------------------
__global__ __launch_bounds__(256) void xproj_kernel(const float* __restrict__ W_xproj) {
    constexpr int ROWS = 16, KC = 64;
    __shared__ float u_s[ROWS][KC];
    __shared__ float W_s[KC][XPROJ_N];
    const int tid = threadIdx.x;
    const int row0 = blockIdx.x * ROWS;
    const int j  = tid % XPROJ_N;
    const int rq = (tid / XPROJ_N) * 4;
    const bool active = tid < 192;

    float acc[4] = {0.f, 0.f, 0.f, 0.f};
    for (int k0 = 0; k0 < D_INNER; k0 += KC) {
        __syncthreads();
        for (int i = tid; i < ROWS * KC; i += 256) {
            const int rr = i >> 6, kk = i & (KC - 1);
            u_s[rr][kk] = g_uc[(size_t)(row0 + rr) * D_INNER + k0 + kk];
        }
        for (int i = tid; i < KC * XPROJ_N; i += 256)
            W_s[i / XPROJ_N][i % XPROJ_N] = W_xproj[(size_t)k0 * XPROJ_N + i];
        __syncthreads();
        if (active) {
#pragma unroll 8
            for (int kk = 0; kk < KC; kk++) {
                const float w = W_s[kk][j];
                acc[0] = fmaf(u_s[rq + 0][kk], w, acc[0]);
                acc[1] = fmaf(u_s[rq + 1][kk], w, acc[1]);
                acc[2] = fmaf(u_s[rq + 2][kk], w, acc[2]);
                acc[3] = fmaf(u_s[rq + 3][kk], w, acc[3]);
            }
        }
    }
    if (active) {
#pragma unroll
        for (int i = 0; i < 4; i++)
            g_xdbl[(size_t)(row0 + rq + i) * XPROJ_N + j] = acc[i];
    }
}

// ---------------------------------------------------------------------------
// K4: SEGMENTED selective scan. Each block handles one (b, seg, 16-d group):
// 256 threads = 16 d x 16 n. Computes per-chain segment summaries assuming
// h_in = 0:  locAcc, coef (=Σ g·C·Πa), Aprod, h_end, plus accD per (d).
// ---------------------------------------------------------------------------
__global__ __launch_bounds__(256) void scan_seg_kernel(const float* __restrict__ A_log,
                                                       const float* __restrict__ W_dt,
                                                       const float* __restrict__ b_dt) {
    constexpr int CH = 32;
    constexpr int PW = 36;
    __shared__ float w_s[16][PW];     // dt           [dd][li]
    __shared__ float wu_s[16][PW];    // dt*u (phase1: u)
    __shared__ float g_s[16][PW];     // gate (phase1: z)
    __shared__ float xd_s[CH * XPROJ_N];
    __shared__ float Wdt_s[DT_RANK][16];
    __shared__ float bdt_s[16];
    __shared__ float accD_red[16][16];

    const int tid = threadIdx.x;
    const int gi = tid >> 4;       // d channel within block
    const int n  = tid & 15;       // state index
    const int blk  = blockIdx.x;
    const int dgrp = blk & 31;
    const int s    = (blk >> 5) & (SEGS - 1);
    const int b    = blk >> 9;
    const int d0 = dgrp * 16;
    const int d  = d0 + gi;
    const int l_base = s * SEG_LEN;

    const int p_dd = tid & 15;
    const int p_li = tid >> 4;

    if (tid < DT_RANK * 16)
        Wdt_s[tid >> 4][tid & 15] = W_dt[(tid >> 4) * D_INNER + d0 + (tid & 15)];
    if (tid < 16) bdt_s[tid] = b_dt[d0 + tid];

    const float A_n = -__expf(A_log[d * D_STATE + n]);

    float h = 0.f, P = 1.f, acc = 0.f, coef = 0.f, accD_th = 0.f;

    for (int l0 = l_base; l0 < l_base + SEG_LEN; l0 += CH) {
        __syncthreads();
        const size_t bl0 = (size_t)(b * SEQ_LEN + l0);
        // phase 1: cooperative loads
        {
            const int dd = tid & 15, li0 = tid >> 4;
#pragma unroll
            for (int q = 0; q < 2; q++) {
                const int li = li0 + q * 16;
                const size_t bl = bl0 + li;
                wu_s[dd][li] = g_uc[bl * D_INNER + d0 + dd];                  // u
                g_s[dd][li]  = g_xz[bl * (2 * D_INNER) + D_INNER + d0 + dd];  // z
            }
        }
#pragma unroll
        for (int q = 0; q < 6; q++) {
            const int i = tid + q * 256;
            if (i < CH * XPROJ_N) xd_s[i] = g_xdbl[bl0 * XPROJ_N + i];
        }
        __syncthreads();
        // phase 2: dt = softplus(xd . W_dt + b), gate = silu(z)
#pragma unroll
        for (int q = 0; q < 2; q++) {
            const int li = p_li + q * 16;
            float dtr = bdt_s[p_dd];
#pragma unroll
            for (int r = 0; r < DT_RANK; r++)
                dtr = fmaf(xd_s[li * XPROJ_N + r], Wdt_s[r][p_dd], dtr);
            const float w = (dtr > 15.0f) ? dtr : log1pf(__expf(dtr));
            const float u = wu_s[p_dd][li];
            const float z = g_s[p_dd][li];
            const float gate = z * __frcp_rn(1.0f + __expf(-z));
            w_s[p_dd][li]  = w;
            wu_s[p_dd][li] = w * u;
            g_s[p_dd][li]  = gate;
            accD_th = fmaf(gate, u, accD_th);
        }
        __syncthreads();
        // phase 3: serial scan over the chunk
#pragma unroll
        for (int l4 = 0; l4 < CH; l4 += 4) {
            const float4 w4  = *(const float4*)&w_s[gi][l4];
            const float4 wu4 = *(const float4*)&wu_s[gi][l4];
            const float4 g4  = *(const float4*)&g_s[gi][l4];
            const float* xb = xd_s + l4 * XPROJ_N + DT_RANK + n;
#pragma unroll
            for (int q = 0; q < 4; q++) {
                const float w  = (q == 0) ? w4.x  : (q == 1) ? w4.y  : (q == 2) ? w4.z  : w4.w;
                const float wu = (q == 0) ? wu4.x : (q == 1) ? wu4.y : (q == 2) ? wu4.z : wu4.w;
                const float gt = (q == 0) ? g4.x  : (q == 1) ? g4.y  : (q == 2) ? g4.z  : g4.w;
                const float bn = xb[q * XPROJ_N];
                const float cn = xb[q * XPROJ_N + D_STATE];
                const float dA = __expf(w * A_n);
                P *= dA;
                h = fmaf(dA, h, wu * bn);
                const float gc = gt * cn;
                acc  = fmaf(gc, h, acc);
                coef = fmaf(gc, P, coef);
            }
        }
    }
    // write packed segment summary (coalesced: tid -> consecutive [d][n])
    const size_t base = ((size_t)(b * SEGS + s) * D_INNER + d0) * D_STATE + tid;
    g_seg[base] = make_float4(acc, coef, P, h);
    // accD reduction over the 16 li-threads per dd
    accD_red[p_li][p_dd] = accD_th;
    __syncthreads();
    if (n == 0) {
        float accD = 0.f;
#pragma unroll
        for (int g = 0; g < 16; g++) accD += accD_red[g][gi];
        g_accD[(size_t)(b * SEGS + s) * D_INNER + d] = accD;
    }
}

// ---------------------------------------------------------------------------
// K5: fixup — combine SEGS segment summaries per chain, reduce over n,
// apply D-skip, write pooled mean.
// ---------------------------------------------------------------------------
__global__ __launch_bounds__(256) void scan_fix_kernel(const float* __restrict__ Dp) {
    const int idx = blockIdx.x * 256 + threadIdx.x;     // over 4*512*16
    const int n = idx & 15;
    const int d = (idx >> 4) & (D_INNER - 1);
    const int b = idx >> 13;

    float carry = 0.f, accT = 0.f, accD = 0.f;
#pragma unroll
    for (int s = 0; s < SEGS; s++) {
        const float4 sg = g_seg[((size_t)(b * SEGS + s) * D_INNER + d) * D_STATE + n];
        accT  = accT + sg.x + sg.y * carry;      // locAcc + coef*carry
        carry = fmaf(sg.z, carry, sg.w);         // Aprod*carry + hend
        if (n == 0) accD += g_accD[(size_t)(b * SEGS + s) * D_INNER + d];
    }
#pragma unroll
    for (int off = 8; off >= 1; off >>= 1)
        accT += __shfl_xor_sync(0xffffffffu, accT, off);
    if (n == 0)
        g_pooled[b * D_INNER + d] = (accT + Dp[d] * accD) * (1.0f / SEQ_LEN);
}

// ---------------------------------------------------------------------------
// K6: logits = (pooled @ W_out) @ W_cls + b_cls   (tiny)
// ---------------------------------------------------------------------------
__global__ __launch_bounds__(256) void final_kernel(const float* __restrict__ W_out,
                                                    const float* __restrict__ W_cls,
                                                    const float* __restrict__ b_cls,
                                                    float* __restrict__ out) {
    __shared__ float p_s[B_SZ * D_INNER];
    __shared__ float t_s[B_SZ * D_MODEL];
    const int tid = threadIdx.x;
    for (int i = tid; i < B_SZ * D_INNER; i += 256) p_s[i] = g_pooled[i];
    __syncthreads();
    float a0 = 0.f, a1 = 0.f, a2 = 0.f, a3 = 0.f;
    for (int k = 0; k < D_INNER; k++) {
        const float w = W_out[k * D_MODEL + tid];
        a0 = fmaf(p_s[k], w, a0);
        a1 = fmaf(p_s[D_INNER + k], w, a1);
        a2 = fmaf(p_s[2 * D_INNER + k], w, a2);
        a3 = fmaf(p_s[3 * D_INNER + k], w, a3);
    }
    t_s[tid] = a0; t_s[D_MODEL + tid] = a1;
    t_s[2 * D_MODEL + tid] = a2; t_s[3 * D_MODEL + tid] = a3;
    __syncthreads();
    if (tid < B_SZ * N_CLS) {
        const int bb = tid / N_CLS, c = tid % N_CLS;
        float acc = b_cls[c];
        for (int k = 0; k < D_MODEL; k++)
            acc = fmaf(t_s[bb * D_MODEL + k], W_cls[k * N_CLS + c], acc);
        out[tid] = acc;
    }
}

// ---------------------------------------------------------------------------
extern "C" void kernel_launch(void* const* d_in, const int* in_sizes, int n_in,
                              void* d_out, int out_size) {
    const float* x       = (const float*)d_in[0];
    const float* W_in    = (const float*)d_in[1];
    const float* W_conv  = (const float*)d_in[2];
    const float* b_conv  = (const float*)d_in[3];
    const float* W_xproj = (const float*)d_in[4];
    const float* W_dt    = (const float*)d_in[5];
    const float* b_dt    = (const float*)d_in[6];
    const float* A_log   = (const float*)d_in[7];
    const float* Dp      = (const float*)d_in[8];
    const float* W_out   = (const float*)d_in[9];
    const float* W_cls   = (const float*)d_in[10];
    const float* b_cls   = (const float*)d_in[11];
    float* out = (float*)d_out;

    gemm1_kernel<<<dim3(2 * D_INNER / 128, BL / 128), 256>>>(x, W_in);
    conv_kernel<<<BL * D_INNER / 256, 256>>>(W_conv, b_conv);
    xproj_kernel<<<BL / 16, 256>>>(W_xproj);
    scan_seg_kernel<<<B_SZ * SEGS * (D_INNER / 16), 256>>>(A_log, W_dt, b_dt);
    scan_fix_kernel<<<B_SZ * D_INNER * D_STATE / 256, 256>>>(Dp);
    final_kernel<<<1, 256>>>(W_out, W_cls, b_cls, out);
}

// round 6
// speedup vs baseline: 2.9041x; 1.3081x over previous
#include <cuda_runtime.h>
#include <math.h>
#include <stdint.h>

// Problem constants
#define B_SZ     4
#define SEQ_LEN  2048
#define D_MODEL  256
#define D_INNER  512
#define D_STATE  16
#define KCONV    4
#define DT_RANK  16
#define N_CLS    10
#define BL       (B_SZ * SEQ_LEN)          // 8192
#define XPROJ_N  (DT_RANK + 2 * D_STATE)   // 48
#define SEGS     16
#define SEG_LEN  (SEQ_LEN / SEGS)          // 128

// Scratch (device globals; no allocation allowed)
__device__ float g_xz[BL * 2 * D_INNER];     // (8192, 1024) : u | silu(z)
__device__ float g_uc[BL * D_INNER];         // (8192, 512)
__device__ float g_xdbl[BL * XPROJ_N];       // (8192, 48)  : dt_raw | Bp | Cp
__device__ float g_pooled[B_SZ * D_INNER];   // (4, 512)
// Segment-scan summaries, packed: [b][seg][d][n] -> {locAcc, coef, Aprod, hend}
__device__ float4 g_seg[B_SZ * SEGS * D_INNER * D_STATE];
__device__ float  g_accD[B_SZ * SEGS * D_INNER];

// ---------------------------------------------------------------------------
// tf32 helpers
// ---------------------------------------------------------------------------
__device__ __forceinline__ uint32_t f2tf32(float f) {
    uint32_t r;
    asm("cvt.rna.tf32.f32 %0, %1;" : "=r"(r) : "f"(f));
    return r;
}

__device__ __forceinline__ void mma_tf32(float& c0, float& c1, float& c2, float& c3,
                                         uint32_t a0, uint32_t a1, uint32_t a2, uint32_t a3,
                                         uint32_t b0, uint32_t b1) {
    asm("mma.sync.aligned.m16n8k8.row.col.f32.tf32.tf32.f32 "
        "{%0,%1,%2,%3},{%4,%5,%6,%7},{%8,%9},{%0,%1,%2,%3};"
        : "+f"(c0), "+f"(c1), "+f"(c2), "+f"(c3)
        : "r"(a0), "r"(a1), "r"(a2), "r"(a3), "r"(b0), "r"(b1));
}

// ---------------------------------------------------------------------------
// K1: xz = x @ W_in  (8192 x 1024, K=256), tf32 tensor cores.
// 128x128x16 block tile, 8 warps (2x4) of 64x32, double-buffered SMEM.
// z-half columns (>=512) get silu applied in the epilogue.
// ---------------------------------------------------------------------------
__global__ __launch_bounds__(256) void gemm1_tc_kernel(const float* __restrict__ A,
                                                       const float* __restrict__ Bm) {
    constexpr int N = 2 * D_INNER, K = D_MODEL;
    constexpr int BM = 128, BN = 128, BK = 16;
    constexpr int NCHUNK = K / BK;                 // 16
    constexpr int ASTR = BK + 4;                   // 20: conflict-free for frag loads
    constexpr int BSTR = BN + 8;                   // 136: conflict-free for frag loads
    __shared__ uint32_t As[2][BM][ASTR];
    __shared__ uint32_t Bs[2][BK][BSTR];

    const int tid  = threadIdx.x;
    const int warp = tid >> 5, lane = tid & 31;
    const int wm = warp & 1, wn = warp >> 1;       // 2 x 4 warp grid
    const int gid = lane >> 2, tig = lane & 3;

    const float* Ab = A + (size_t)blockIdx.y * BM * K;
    const float* Bb = Bm + blockIdx.x * BN;

    // A loader: 512 float4 (128 rows x 4), 2 per thread
    const int a_r0 = tid >> 2, a_c4 = (tid & 3) << 2;          // rows 0..63 / +64
    // B loader: 512 float4 (16 rows x 32), 2 per thread
    const int b_r0 = tid >> 5, b_c4 = (tid & 31) << 2;         // rows 0..7 / +8

    float acc[4][4][4];
#pragma unroll
    for (int mi = 0; mi < 4; mi++)
#pragma unroll
        for (int ni = 0; ni < 4; ni++)
#pragma unroll
            for (int q = 0; q < 4; q++) acc[mi][ni][q] = 0.f;

    float4 pa[2], pb[2];
    pa[0] = *(const float4*)(Ab + a_r0 * K + a_c4);
    pa[1] = *(const float4*)(Ab + (a_r0 + 64) * K + a_c4);
    pb[0] = *(const float4*)(Bb + b_r0 * N + b_c4);
    pb[1] = *(const float4*)(Bb + (b_r0 + 8) * N + b_c4);
#pragma unroll
    for (int i = 0; i < 2; i++) {
        const int ar = a_r0 + i * 64;
        As[0][ar][a_c4 + 0] = f2tf32(pa[i].x); As[0][ar][a_c4 + 1] = f2tf32(pa[i].y);
        As[0][ar][a_c4 + 2] = f2tf32(pa[i].z); As[0][ar][a_c4 + 3] = f2tf32(pa[i].w);
        const int br = b_r0 + i * 8;
        Bs[0][br][b_c4 + 0] = f2tf32(pb[i].x); Bs[0][br][b_c4 + 1] = f2tf32(pb[i].y);
        Bs[0][br][b_c4 + 2] = f2tf32(pb[i].z); Bs[0][br][b_c4 + 3] = f2tf32(pb[i].w);
    }
    __syncthreads();

    int buf = 0;
    for (int c = 0; c < NCHUNK; c++) {
        if (c + 1 < NCHUNK) {
            const int k0 = (c + 1) * BK;
            pa[0] = *(const float4*)(Ab + a_r0 * K + k0 + a_c4);
            pa[1] = *(const float4*)(Ab + (a_r0 + 64) * K + k0 + a_c4);
            pb[0] = *(const float4*)(Bb + (k0 + b_r0) * N + b_c4);
            pb[1] = *(const float4*)(Bb + (k0 + b_r0 + 8) * N + b_c4);
        }
#pragma unroll
        for (int ks = 0; ks < BK; ks += 8) {
            uint32_t af[4][4], bf[4][2];
#pragma unroll
            for (int mi = 0; mi < 4; mi++) {
                const int r = wm * 64 + mi * 16 + gid;
                af[mi][0] = As[buf][r][ks + tig];
                af[mi][1] = As[buf][r + 8][ks + tig];
                af[mi][2] = As[buf][r][ks + tig + 4];
                af[mi][3] = As[buf][r + 8][ks + tig + 4];
            }
#pragma unroll
            for (int ni = 0; ni < 4; ni++) {
                const int cc = wn * 32 + ni * 8 + gid;
                bf[ni][0] = Bs[buf][ks + tig][cc];
                bf[ni][1] = Bs[buf][ks + tig + 4][cc];
            }
#pragma unroll
            for (int mi = 0; mi < 4; mi++)
#pragma unroll
                for (int ni = 0; ni < 4; ni++)
                    mma_tf32(acc[mi][ni][0], acc[mi][ni][1], acc[mi][ni][2], acc[mi][ni][3],
                             af[mi][0], af[mi][1], af[mi][2], af[mi][3],
                             bf[ni][0], bf[ni][1]);
        }
        if (c + 1 < NCHUNK) {
            const int nb = buf ^ 1;
#pragma unroll
            for (int i = 0; i < 2; i++) {
                const int ar = a_r0 + i * 64;
                As[nb][ar][a_c4 + 0] = f2tf32(pa[i].x); As[nb][ar][a_c4 + 1] = f2tf32(pa[i].y);
                As[nb][ar][a_c4 + 2] = f2tf32(pa[i].z); As[nb][ar][a_c4 + 3] = f2tf32(pa[i].w);
                const int br = b_r0 + i * 8;
                Bs[nb][br][b_c4 + 0] = f2tf32(pb[i].x); Bs[nb][br][b_c4 + 1] = f2tf32(pb[i].y);
                Bs[nb][br][b_c4 + 2] = f2tf32(pb[i].z); Bs[nb][br][b_c4 + 3] = f2tf32(pb[i].w);
            }
            __syncthreads();
            buf ^= 1;
        }
    }

    // epilogue: silu on z-half (cols >= 512 -> blockIdx.x >= 4)
    const bool is_z = (blockIdx.x >= (D_INNER / BN));
    float* Cb = g_xz + (size_t)blockIdx.y * BM * N + blockIdx.x * BN;
#pragma unroll
    for (int mi = 0; mi < 4; mi++) {
#pragma unroll
        for (int ni = 0; ni < 4; ni++) {
            const int row = wm * 64 + mi * 16 + gid;
            const int col = wn * 32 + ni * 8 + 2 * tig;
            float v0 = acc[mi][ni][0], v1 = acc[mi][ni][1];
            float v2 = acc[mi][ni][2], v3 = acc[mi][ni][3];
            if (is_z) {
                v0 = v0 * __frcp_rn(1.0f + __expf(-v0));
                v1 = v1 * __frcp_rn(1.0f + __expf(-v1));
                v2 = v2 * __frcp_rn(1.0f + __expf(-v2));
                v3 = v3 * __frcp_rn(1.0f + __expf(-v3));
            }
            *(float2*)(Cb + (size_t)row * N + col) = make_float2(v0, v1);
            *(float2*)(Cb + (size_t)(row + 8) * N + col) = make_float2(v2, v3);
        }
    }
}

// ---------------------------------------------------------------------------
// K2: depthwise causal conv (K=4) + bias + SiLU -> u_c
// ---------------------------------------------------------------------------
__global__ __launch_bounds__(256) void conv_kernel(const float* __restrict__ W_conv,
                                                   const float* __restrict__ b_conv) {
    const int idx = blockIdx.x * 256 + threadIdx.x;        // over 8192*512
    const int d  = idx & (D_INNER - 1);
    const int bl = idx >> 9;
    const int l  = bl & (SEQ_LEN - 1);
    const int b  = bl >> 11;
    float acc = b_conv[d];
#pragma unroll
    for (int k = 0; k < KCONV; k++) {
        const int ll = l + k - (KCONV - 1);
        if (ll >= 0)
            acc = fmaf(g_xz[(size_t)(b * SEQ_LEN + ll) * (2 * D_INNER) + d],
                       W_conv[d * KCONV + k], acc);
    }
    g_uc[idx] = acc * __frcp_rn(1.0f + __expf(-acc));  // silu
}

// ---------------------------------------------------------------------------
// K3: x_dbl = u_c @ W_xproj    (8192 x 48, K=512); 16 rows per block.
// ---------------------------------------------------------------------------
__global__ __launch_bounds__(256) void xproj_kernel(const float* __restrict__ W_xproj) {
    constexpr int ROWS = 16, KC = 64;
    __shared__ float u_s[ROWS][KC];
    __shared__ float W_s[KC][XPROJ_N];
    const int tid = threadIdx.x;
    const int row0 = blockIdx.x * ROWS;
    const int j  = tid % XPROJ_N;
    const int rq = (tid / XPROJ_N) * 4;
    const bool active = tid < 192;

    float acc[4] = {0.f, 0.f, 0.f, 0.f};
    for (int k0 = 0; k0 < D_INNER; k0 += KC) {
        __syncthreads();
        for (int i = tid; i < ROWS * KC; i += 256) {
            const int rr = i >> 6, kk = i & (KC - 1);
            u_s[rr][kk] = g_uc[(size_t)(row0 + rr) * D_INNER + k0 + kk];
        }
        for (int i = tid; i < KC * XPROJ_N; i += 256)
            W_s[i / XPROJ_N][i % XPROJ_N] = W_xproj[(size_t)k0 * XPROJ_N + i];
        __syncthreads();
        if (active) {
#pragma unroll 8
            for (int kk = 0; kk < KC; kk++) {
                const float w = W_s[kk][j];
                acc[0] = fmaf(u_s[rq + 0][kk], w, acc[0]);
                acc[1] = fmaf(u_s[rq + 1][kk], w, acc[1]);
                acc[2] = fmaf(u_s[rq + 2][kk], w, acc[2]);
                acc[3] = fmaf(u_s[rq + 3][kk], w, acc[3]);
            }
        }
    }
    if (active) {
#pragma unroll
        for (int i = 0; i < 4; i++)
            g_xdbl[(size_t)(row0 + rq + i) * XPROJ_N + j] = acc[i];
    }
}

// ---------------------------------------------------------------------------
// K4: SEGMENTED selective scan. Each block handles one (b, seg, 16-d group):
// 256 threads = 16 d x 16 n. z-half of g_xz already holds silu(z) = gate.
// ---------------------------------------------------------------------------
__global__ __launch_bounds__(256) void scan_seg_kernel(const float* __restrict__ A_log,
                                                       const float* __restrict__ W_dt,
                                                       const float* __restrict__ b_dt) {
    constexpr int CH = 32;
    constexpr int PW = 36;
    __shared__ float w_s[16][PW];     // dt           [dd][li]
    __shared__ float wu_s[16][PW];    // dt*u (phase1: u)
    __shared__ float g_s[16][PW];     // gate
    __shared__ float xd_s[CH * XPROJ_N];
    __shared__ float Wdt_s[DT_RANK][16];
    __shared__ float bdt_s[16];
    __shared__ float accD_red[16][16];

    const int tid = threadIdx.x;
    const int gi = tid >> 4;       // d channel within block
    const int n  = tid & 15;       // state index
    const int blk  = blockIdx.x;
    const int dgrp = blk & 31;
    const int s    = (blk >> 5) & (SEGS - 1);
    const int b    = blk >> 9;
    const int d0 = dgrp * 16;
    const int d  = d0 + gi;
    const int l_base = s * SEG_LEN;

    const int p_dd = tid & 15;
    const int p_li = tid >> 4;

    if (tid < DT_RANK * 16)
        Wdt_s[tid >> 4][tid & 15] = W_dt[(tid >> 4) * D_INNER + d0 + (tid & 15)];
    if (tid < 16) bdt_s[tid] = b_dt[d0 + tid];

    const float A_n = -__expf(A_log[d * D_STATE + n]);

    float h = 0.f, P = 1.f, acc = 0.f, coef = 0.f, accD_th = 0.f;

    for (int l0 = l_base; l0 < l_base + SEG_LEN; l0 += CH) {
        __syncthreads();
        const size_t bl0 = (size_t)(b * SEQ_LEN + l0);
        // phase 1: cooperative loads (gate comes pre-silu'd from GEMM epilogue)
        {
            const int dd = tid & 15, li0 = tid >> 4;
#pragma unroll
            for (int q = 0; q < 2; q++) {
                const int li = li0 + q * 16;
                const size_t bl = bl0 + li;
                wu_s[dd][li] = g_uc[bl * D_INNER + d0 + dd];                  // u
                g_s[dd][li]  = g_xz[bl * (2 * D_INNER) + D_INNER + d0 + dd];  // gate
            }
        }
#pragma unroll
        for (int q = 0; q < 6; q++) {
            const int i = tid + q * 256;
            if (i < CH * XPROJ_N) xd_s[i] = g_xdbl[bl0 * XPROJ_N + i];
        }
        __syncthreads();
        // phase 2: dt = softplus(xd . W_dt + b); wu = dt*u; accD += gate*u
#pragma unroll
        for (int q = 0; q < 2; q++) {
            const int li = p_li + q * 16;
            float dtr = bdt_s[p_dd];
#pragma unroll
            for (int r = 0; r < DT_RANK; r++)
                dtr = fmaf(xd_s[li * XPROJ_N + r], Wdt_s[r][p_dd], dtr);
            const float w = (dtr > 15.0f) ? dtr : log1pf(__expf(dtr));
            const float u = wu_s[p_dd][li];
            const float gate = g_s[p_dd][li];
            w_s[p_dd][li]  = w;
            wu_s[p_dd][li] = w * u;
            accD_th = fmaf(gate, u, accD_th);
        }
        __syncthreads();
        // phase 3: serial scan over the chunk
#pragma unroll
        for (int l4 = 0; l4 < CH; l4 += 4) {
            const float4 w4  = *(const float4*)&w_s[gi][l4];
            const float4 wu4 = *(const float4*)&wu_s[gi][l4];
            const float4 g4  = *(const float4*)&g_s[gi][l4];
            const float* xb = xd_s + l4 * XPROJ_N + DT_RANK + n;
#pragma unroll
            for (int q = 0; q < 4; q++) {
                const float w  = (q == 0) ? w4.x  : (q == 1) ? w4.y  : (q == 2) ? w4.z  : w4.w;
                const float wu = (q == 0) ? wu4.x : (q == 1) ? wu4.y : (q == 2) ? wu4.z : wu4.w;
                const float gt = (q == 0) ? g4.x  : (q == 1) ? g4.y  : (q == 2) ? g4.z  : g4.w;
                const float bn = xb[q * XPROJ_N];
                const float cn = xb[q * XPROJ_N + D_STATE];
                const float dA = __expf(w * A_n);
                P *= dA;
                h = fmaf(dA, h, wu * bn);
                const float gc = gt * cn;
                acc  = fmaf(gc, h, acc);
                coef = fmaf(gc, P, coef);
            }
        }
    }
    // write packed segment summary (coalesced: tid -> consecutive [d][n])
    const size_t base = ((size_t)(b * SEGS + s) * D_INNER + d0) * D_STATE + tid;
    g_seg[base] = make_float4(acc, coef, P, h);
    // accD reduction over the 16 li-threads per dd
    accD_red[p_li][p_dd] = accD_th;
    __syncthreads();
    if (n == 0) {
        float accD = 0.f;
#pragma unroll
        for (int g = 0; g < 16; g++) accD += accD_red[g][gi];
        g_accD[(size_t)(b * SEGS + s) * D_INNER + d] = accD;
    }
}

// ---------------------------------------------------------------------------
// K5: fixup — combine SEGS segment summaries per chain, reduce over n,
// apply D-skip, write pooled mean.
// ---------------------------------------------------------------------------
__global__ __launch_bounds__(256) void scan_fix_kernel(const float* __restrict__ Dp) {
    const int idx = blockIdx.x * 256 + threadIdx.x;     // over 4*512*16
    const int n = idx & 15;
    const int d = (idx >> 4) & (D_INNER - 1);
    const int b = idx >> 13;

    float carry = 0.f, accT = 0.f, accD = 0.f;
#pragma unroll
    for (int s = 0; s < SEGS; s++) {
        const float4 sg = g_seg[((size_t)(b * SEGS + s) * D_INNER + d) * D_STATE + n];
        accT  = accT + sg.x + sg.y * carry;      // locAcc + coef*carry
        carry = fmaf(sg.z, carry, sg.w);         // Aprod*carry + hend
        if (n == 0) accD += g_accD[(size_t)(b * SEGS + s) * D_INNER + d];
    }
#pragma unroll
    for (int off = 8; off >= 1; off >>= 1)
        accT += __shfl_xor_sync(0xffffffffu, accT, off);
    if (n == 0)
        g_pooled[b * D_INNER + d] = (accT + Dp[d] * accD) * (1.0f / SEQ_LEN);
}

// ---------------------------------------------------------------------------
// K6: logits = (pooled @ W_out) @ W_cls + b_cls   (tiny)
// ---------------------------------------------------------------------------
__global__ __launch_bounds__(256) void final_kernel(const float* __restrict__ W_out,
                                                    const float* __restrict__ W_cls,
                                                    const float* __restrict__ b_cls,
                                                    float* __restrict__ out) {
    __shared__ float p_s[B_SZ * D_INNER];
    __shared__ float t_s[B_SZ * D_MODEL];
    const int tid = threadIdx.x;
    for (int i = tid; i < B_SZ * D_INNER; i += 256) p_s[i] = g_pooled[i];
    __syncthreads();
    float a0 = 0.f, a1 = 0.f, a2 = 0.f, a3 = 0.f;
    for (int k = 0; k < D_INNER; k++) {
        const float w = W_out[k * D_MODEL + tid];
        a0 = fmaf(p_s[k], w, a0);
        a1 = fmaf(p_s[D_INNER + k], w, a1);
        a2 = fmaf(p_s[2 * D_INNER + k], w, a2);
        a3 = fmaf(p_s[3 * D_INNER + k], w, a3);
    }
    t_s[tid] = a0; t_s[D_MODEL + tid] = a1;
    t_s[2 * D_MODEL + tid] = a2; t_s[3 * D_MODEL + tid] = a3;
    __syncthreads();
    if (tid < B_SZ * N_CLS) {
        const int bb = tid / N_CLS, c = tid % N_CLS;
        float acc = b_cls[c];
        for (int k = 0; k < D_MODEL; k++)
            acc = fmaf(t_s[bb * D_MODEL + k], W_cls[k * N_CLS + c], acc);
        out[tid] = acc;
    }
}

// ---------------------------------------------------------------------------
extern "C" void kernel_launch(void* const* d_in, const int* in_sizes, int n_in,
                              void* d_out, int out_size) {
    const float* x       = (const float*)d_in[0];
    const float* W_in    = (const float*)d_in[1];
    const float* W_conv  = (const float*)d_in[2];
    const float* b_conv  = (const float*)d_in[3];
    const float* W_xproj = (const float*)d_in[4];
    const float* W_dt    = (const float*)d_in[5];
    const float* b_dt    = (const float*)d_in[6];
    const float* A_log   = (const float*)d_in[7];
    const float* Dp      = (const float*)d_in[8];
    const float* W_out   = (const float*)d_in[9];
    const float* W_cls   = (const float*)d_in[10];
    const float* b_cls   = (const float*)d_in[11];
    float* out = (float*)d_out;

    gemm1_tc_kernel<<<dim3(2 * D_INNER / 128, BL / 128), 256>>>(x, W_in);
    conv_kernel<<<BL * D_INNER / 256, 256>>>(W_conv, b_conv);
    xproj_kernel<<<BL / 16, 256>>>(W_xproj);
    scan_seg_kernel<<<B_SZ * SEGS * (D_INNER / 16), 256>>>(A_log, W_dt, b_dt);
    scan_fix_kernel<<<B_SZ * D_INNER * D_STATE / 256, 256>>>(Dp);
    final_kernel<<<1, 256>>>(W_out, W_cls, b_cls, out);
}

// round 7
// speedup vs baseline: 3.0849x; 1.0622x over previous
#include <cuda_runtime.h>
#include <math.h>
#include <stdint.h>

// Problem constants
#define B_SZ     4
#define SEQ_LEN  2048
#define D_MODEL  256
#define D_INNER  512
#define D_STATE  16
#define KCONV    4
#define DT_RANK  16
#define N_CLS    10
#define BL       (B_SZ * SEQ_LEN)          // 8192
#define XPROJ_N  (DT_RANK + 2 * D_STATE)   // 48
#define SEGS     16
#define SEG_LEN  (SEQ_LEN / SEGS)          // 128

// Scratch (device globals; no allocation allowed)
__device__ float g_xz[BL * 2 * D_INNER];     // (8192, 1024) : u | silu(z)
__device__ float g_uc[BL * D_INNER];         // (8192, 512)
__device__ float g_xdbl[BL * XPROJ_N];       // (8192, 48)  : dt_raw | Bp | Cp
__device__ float g_pooled[B_SZ * D_INNER];   // (4, 512)
// Segment-scan summaries, packed: [b][seg][d][n] -> {locAcc, coef, Aprod, hend}
__device__ float4 g_seg[B_SZ * SEGS * D_INNER * D_STATE];
__device__ float  g_accD[B_SZ * SEGS * D_INNER];

// ---------------------------------------------------------------------------
// tf32 helpers
// ---------------------------------------------------------------------------
__device__ __forceinline__ uint32_t f2tf32(float f) {
    uint32_t r;
    asm("cvt.rna.tf32.f32 %0, %1;" : "=r"(r) : "f"(f));
    return r;
}

__device__ __forceinline__ void split_tf32(float v, uint32_t& hi, uint32_t& lo) {
    hi = f2tf32(v);
    lo = f2tf32(v - __uint_as_float(hi));
}

__device__ __forceinline__ void mma_tf32(float& c0, float& c1, float& c2, float& c3,
                                         uint32_t a0, uint32_t a1, uint32_t a2, uint32_t a3,
                                         uint32_t b0, uint32_t b1) {
    asm("mma.sync.aligned.m16n8k8.row.col.f32.tf32.tf32.f32 "
        "{%0,%1,%2,%3},{%4,%5,%6,%7},{%8,%9},{%0,%1,%2,%3};"
        : "+f"(c0), "+f"(c1), "+f"(c2), "+f"(c3)
        : "r"(a0), "r"(a1), "r"(a2), "r"(a3), "r"(b0), "r"(b1));
}

// ---------------------------------------------------------------------------
// K1: xz = x @ W_in  (8192 x 1024, K=256), tf32 tensor cores (single pass).
// 128x128x16 block tile, 8 warps (2x4) of 64x32, double-buffered SMEM.
// z-half columns (>=512) get silu applied in the epilogue.
// ---------------------------------------------------------------------------
__global__ __launch_bounds__(256) void gemm1_tc_kernel(const float* __restrict__ A,
                                                       const float* __restrict__ Bm) {
    constexpr int N = 2 * D_INNER, K = D_MODEL;
    constexpr int BM = 128, BN = 128, BK = 16;
    constexpr int NCHUNK = K / BK;                 // 16
    constexpr int ASTR = BK + 4;                   // 20
    constexpr int BSTR = BN + 8;                   // 136
    __shared__ uint32_t As[2][BM][ASTR];
    __shared__ uint32_t Bs[2][BK][BSTR];

    const int tid  = threadIdx.x;
    const int warp = tid >> 5, lane = tid & 31;
    const int wm = warp & 1, wn = warp >> 1;       // 2 x 4 warp grid
    const int gid = lane >> 2, tig = lane & 3;

    const float* Ab = A + (size_t)blockIdx.y * BM * K;
    const float* Bb = Bm + blockIdx.x * BN;

    const int a_r0 = tid >> 2, a_c4 = (tid & 3) << 2;
    const int b_r0 = tid >> 5, b_c4 = (tid & 31) << 2;

    float acc[4][4][4];
#pragma unroll
    for (int mi = 0; mi < 4; mi++)
#pragma unroll
        for (int ni = 0; ni < 4; ni++)
#pragma unroll
            for (int q = 0; q < 4; q++) acc[mi][ni][q] = 0.f;

    float4 pa[2], pb[2];
    pa[0] = *(const float4*)(Ab + a_r0 * K + a_c4);
    pa[1] = *(const float4*)(Ab + (a_r0 + 64) * K + a_c4);
    pb[0] = *(const float4*)(Bb + b_r0 * N + b_c4);
    pb[1] = *(const float4*)(Bb + (b_r0 + 8) * N + b_c4);
#pragma unroll
    for (int i = 0; i < 2; i++) {
        const int ar = a_r0 + i * 64;
        As[0][ar][a_c4 + 0] = f2tf32(pa[i].x); As[0][ar][a_c4 + 1] = f2tf32(pa[i].y);
        As[0][ar][a_c4 + 2] = f2tf32(pa[i].z); As[0][ar][a_c4 + 3] = f2tf32(pa[i].w);
        const int br = b_r0 + i * 8;
        Bs[0][br][b_c4 + 0] = f2tf32(pb[i].x); Bs[0][br][b_c4 + 1] = f2tf32(pb[i].y);
        Bs[0][br][b_c4 + 2] = f2tf32(pb[i].z); Bs[0][br][b_c4 + 3] = f2tf32(pb[i].w);
    }
    __syncthreads();

    int buf = 0;
    for (int c = 0; c < NCHUNK; c++) {
        if (c + 1 < NCHUNK) {
            const int k0 = (c + 1) * BK;
            pa[0] = *(const float4*)(Ab + a_r0 * K + k0 + a_c4);
            pa[1] = *(const float4*)(Ab + (a_r0 + 64) * K + k0 + a_c4);
            pb[0] = *(const float4*)(Bb + (k0 + b_r0) * N + b_c4);
            pb[1] = *(const float4*)(Bb + (k0 + b_r0 + 8) * N + b_c4);
        }
#pragma unroll
        for (int ks = 0; ks < BK; ks += 8) {
            uint32_t af[4][4], bf[4][2];
#pragma unroll
            for (int mi = 0; mi < 4; mi++) {
                const int r = wm * 64 + mi * 16 + gid;
                af[mi][0] = As[buf][r][ks + tig];
                af[mi][1] = As[buf][r + 8][ks + tig];
                af[mi][2] = As[buf][r][ks + tig + 4];
                af[mi][3] = As[buf][r + 8][ks + tig + 4];
            }
#pragma unroll
            for (int ni = 0; ni < 4; ni++) {
                const int cc = wn * 32 + ni * 8 + gid;
                bf[ni][0] = Bs[buf][ks + tig][cc];
                bf[ni][1] = Bs[buf][ks + tig + 4][cc];
            }
#pragma unroll
            for (int mi = 0; mi < 4; mi++)
#pragma unroll
                for (int ni = 0; ni < 4; ni++)
                    mma_tf32(acc[mi][ni][0], acc[mi][ni][1], acc[mi][ni][2], acc[mi][ni][3],
                             af[mi][0], af[mi][1], af[mi][2], af[mi][3],
                             bf[ni][0], bf[ni][1]);
        }
        if (c + 1 < NCHUNK) {
            const int nb = buf ^ 1;
#pragma unroll
            for (int i = 0; i < 2; i++) {
                const int ar = a_r0 + i * 64;
                As[nb][ar][a_c4 + 0] = f2tf32(pa[i].x); As[nb][ar][a_c4 + 1] = f2tf32(pa[i].y);
                As[nb][ar][a_c4 + 2] = f2tf32(pa[i].z); As[nb][ar][a_c4 + 3] = f2tf32(pa[i].w);
                const int br = b_r0 + i * 8;
                Bs[nb][br][b_c4 + 0] = f2tf32(pb[i].x); Bs[nb][br][b_c4 + 1] = f2tf32(pb[i].y);
                Bs[nb][br][b_c4 + 2] = f2tf32(pb[i].z); Bs[nb][br][b_c4 + 3] = f2tf32(pb[i].w);
            }
            __syncthreads();
            buf ^= 1;
        }
    }

    const bool is_z = (blockIdx.x >= (D_INNER / BN));
    float* Cb = g_xz + (size_t)blockIdx.y * BM * N + blockIdx.x * BN;
#pragma unroll
    for (int mi = 0; mi < 4; mi++) {
#pragma unroll
        for (int ni = 0; ni < 4; ni++) {
            const int row = wm * 64 + mi * 16 + gid;
            const int col = wn * 32 + ni * 8 + 2 * tig;
            float v0 = acc[mi][ni][0], v1 = acc[mi][ni][1];
            float v2 = acc[mi][ni][2], v3 = acc[mi][ni][3];
            if (is_z) {
                v0 = v0 * __frcp_rn(1.0f + __expf(-v0));
                v1 = v1 * __frcp_rn(1.0f + __expf(-v1));
                v2 = v2 * __frcp_rn(1.0f + __expf(-v2));
                v3 = v3 * __frcp_rn(1.0f + __expf(-v3));
            }
            *(float2*)(Cb + (size_t)row * N + col) = make_float2(v0, v1);
            *(float2*)(Cb + (size_t)(row + 8) * N + col) = make_float2(v2, v3);
        }
    }
}

// ---------------------------------------------------------------------------
// K2: depthwise causal conv (K=4) + bias + SiLU -> u_c
// ---------------------------------------------------------------------------
__global__ __launch_bounds__(256) void conv_kernel(const float* __restrict__ W_conv,
                                                   const float* __restrict__ b_conv) {
    const int idx = blockIdx.x * 256 + threadIdx.x;        // over 8192*512
    const int d  = idx & (D_INNER - 1);
    const int bl = idx >> 9;
    const int l  = bl & (SEQ_LEN - 1);
    const int b  = bl >> 11;
    float acc = b_conv[d];
#pragma unroll
    for (int k = 0; k < KCONV; k++) {
        const int ll = l + k - (KCONV - 1);
        if (ll >= 0)
            acc = fmaf(g_xz[(size_t)(b * SEQ_LEN + ll) * (2 * D_INNER) + d],
                       W_conv[d * KCONV + k], acc);
    }
    g_uc[idx] = acc * __frcp_rn(1.0f + __expf(-acc));  // silu
}

// ---------------------------------------------------------------------------
// K3: x_dbl = u_c @ W_xproj  (8192 x 48, K=512), tensor cores with 3-pass
// split-tf32 (error ~1e-7, adds nothing to global rel_err).
// 64x64 block tile (N padded 48->64), 8 warps (2x4) of 32x16.
// ---------------------------------------------------------------------------
__global__ __launch_bounds__(256) void xproj_tc_kernel(const float* __restrict__ W) {
    constexpr int K = D_INNER;          // 512
    constexpr int BM = 64, BN = 64, BK = 16;
    constexpr int NCHUNK = K / BK;      // 32
    constexpr int ASTR = BK + 4;        // 20
    constexpr int BSTR = BN + 8;        // 72
    __shared__ float As[2][BM][ASTR];
    __shared__ float Bs[2][BK][BSTR];

    const int tid  = threadIdx.x;
    const int warp = tid >> 5, lane = tid & 31;
    const int wm = warp & 1, wn = warp >> 1;     // 2 x 4
    const int gid = lane >> 2, tig = lane & 3;

    const float* Ab = g_uc + (size_t)blockIdx.x * BM * K;
    const int a_r = tid >> 2, a_c4 = (tid & 3) << 2;     // 64 rows x 16 cols

    float acc[2][2][4];
#pragma unroll
    for (int mi = 0; mi < 2; mi++)
#pragma unroll
        for (int ni = 0; ni < 2; ni++)
#pragma unroll
            for (int q = 0; q < 4; q++) acc[mi][ni][q] = 0.f;

    // prologue: chunk 0
    {
        *(float4*)&As[0][a_r][a_c4] = *(const float4*)(Ab + a_r * K + a_c4);
#pragma unroll
        for (int s = 0; s < 4; s++) {
            const int i = tid + s * 256;
            const int kk = i >> 6, nn = i & 63;
            Bs[0][kk][nn] = (nn < XPROJ_N) ? W[kk * XPROJ_N + nn] : 0.f;
        }
    }
    __syncthreads();

    int buf = 0;
    for (int c = 0; c < NCHUNK; c++) {
        float4 pa;
        float pbv[4];
        if (c + 1 < NCHUNK) {
            const int k0 = (c + 1) * BK;
            pa = *(const float4*)(Ab + a_r * K + k0 + a_c4);
#pragma unroll
            for (int s = 0; s < 4; s++) {
                const int i = tid + s * 256;
                const int kk = i >> 6, nn = i & 63;
                pbv[s] = (nn < XPROJ_N) ? W[(k0 + kk) * XPROJ_N + nn] : 0.f;
            }
        }
#pragma unroll
        for (int ks = 0; ks < BK; ks += 8) {
            uint32_t ahi[2][4], alo[2][4], bhi[2][2], blo[2][2];
#pragma unroll
            for (int mi = 0; mi < 2; mi++) {
                const int r = wm * 32 + mi * 16 + gid;
                split_tf32(As[buf][r][ks + tig],         ahi[mi][0], alo[mi][0]);
                split_tf32(As[buf][r + 8][ks + tig],     ahi[mi][1], alo[mi][1]);
                split_tf32(As[buf][r][ks + tig + 4],     ahi[mi][2], alo[mi][2]);
                split_tf32(As[buf][r + 8][ks + tig + 4], ahi[mi][3], alo[mi][3]);
            }
#pragma unroll
            for (int ni = 0; ni < 2; ni++) {
                const int cc = wn * 16 + ni * 8 + gid;
                split_tf32(Bs[buf][ks + tig][cc],     bhi[ni][0], blo[ni][0]);
                split_tf32(Bs[buf][ks + tig + 4][cc], bhi[ni][1], blo[ni][1]);
            }
#pragma unroll
            for (int mi = 0; mi < 2; mi++)
#pragma unroll
                for (int ni = 0; ni < 2; ni++) {
                    mma_tf32(acc[mi][ni][0], acc[mi][ni][1], acc[mi][ni][2], acc[mi][ni][3],
                             ahi[mi][0], ahi[mi][1], ahi[mi][2], ahi[mi][3],
                             bhi[ni][0], bhi[ni][1]);
                    mma_tf32(acc[mi][ni][0], acc[mi][ni][1], acc[mi][ni][2], acc[mi][ni][3],
                             alo[mi][0], alo[mi][1], alo[mi][2], alo[mi][3],
                             bhi[ni][0], bhi[ni][1]);
                    mma_tf32(acc[mi][ni][0], acc[mi][ni][1], acc[mi][ni][2], acc[mi][ni][3],
                             ahi[mi][0], ahi[mi][1], ahi[mi][2], ahi[mi][3],
                             blo[ni][0], blo[ni][1]);
                }
        }
        if (c + 1 < NCHUNK) {
            const int nb = buf ^ 1;
            *(float4*)&As[nb][a_r][a_c4] = pa;
#pragma unroll
            for (int s = 0; s < 4; s++) {
                const int i = tid + s * 256;
                const int kk = i >> 6, nn = i & 63;
                Bs[nb][kk][nn] = pbv[s];
            }
            __syncthreads();
            buf ^= 1;
        }
    }

    const size_t row0 = (size_t)blockIdx.x * BM;
#pragma unroll
    for (int mi = 0; mi < 2; mi++) {
#pragma unroll
        for (int ni = 0; ni < 2; ni++) {
            const int row = wm * 32 + mi * 16 + gid;
            const int col = wn * 16 + ni * 8 + 2 * tig;
            if (col < XPROJ_N) {
                *(float2*)(g_xdbl + (row0 + row) * XPROJ_N + col) =
                    make_float2(acc[mi][ni][0], acc[mi][ni][1]);
                *(float2*)(g_xdbl + (row0 + row + 8) * XPROJ_N + col) =
                    make_float2(acc[mi][ni][2], acc[mi][ni][3]);
            }
        }
    }
}

// ---------------------------------------------------------------------------
// K4: SEGMENTED selective scan. Each block: one (b, seg, 16-d group);
// 256 threads = 16 d x 16 n. Bp/Cp transposed into [n][li] SMEM so the
// serial loop reads them as LDS.128 instead of 8 scalar LDS per 4 steps.
// ---------------------------------------------------------------------------
__global__ __launch_bounds__(256) void scan_seg_kernel(const float* __restrict__ A_log,
                                                       const float* __restrict__ W_dt,
                                                       const float* __restrict__ b_dt) {
    constexpr int CH = 32;
    constexpr int PW = 36;
    __shared__ float w_s[16][PW];     // dt           [dd][li]
    __shared__ float wu_s[16][PW];    // dt*u (phase1: u)
    __shared__ float g_s[16][PW];     // gate
    __shared__ float bp_s[16][PW];    // Bp transposed [n][li]
    __shared__ float cp_s[16][PW];    // Cp transposed [n][li]
    __shared__ float xd_s[CH * XPROJ_N];
    __shared__ float Wdt_s[DT_RANK][16];
    __shared__ float bdt_s[16];
    __shared__ float accD_red[16][16];

    const int tid = threadIdx.x;
    const int gi = tid >> 4;       // d channel within block
    const int n  = tid & 15;       // state index
    const int blk  = blockIdx.x;
    const int dgrp = blk & 31;
    const int s    = (blk >> 5) & (SEGS - 1);
    const int b    = blk >> 9;
    const int d0 = dgrp * 16;
    const int d  = d0 + gi;
    const int l_base = s * SEG_LEN;

    const int p_dd = tid & 15;
    const int p_li = tid >> 4;

    if (tid < DT_RANK * 16)
        Wdt_s[tid >> 4][tid & 15] = W_dt[(tid >> 4) * D_INNER + d0 + (tid & 15)];
    if (tid < 16) bdt_s[tid] = b_dt[d0 + tid];

    const float A_n = -__expf(A_log[d * D_STATE + n]);

    float h = 0.f, P = 1.f, acc = 0.f, coef = 0.f, accD_th = 0.f;

    for (int l0 = l_base; l0 < l_base + SEG_LEN; l0 += CH) {
        __syncthreads();
        const size_t bl0 = (size_t)(b * SEQ_LEN + l0);
        // phase 1: cooperative loads (gate pre-silu'd by GEMM epilogue)
        {
            const int dd = tid & 15, li0 = tid >> 4;
#pragma unroll
            for (int q = 0; q < 2; q++) {
                const int li = li0 + q * 16;
                const size_t bl = bl0 + li;
                wu_s[dd][li] = g_uc[bl * D_INNER + d0 + dd];                  // u
                g_s[dd][li]  = g_xz[bl * (2 * D_INNER) + D_INNER + d0 + dd];  // gate
            }
        }
#pragma unroll
        for (int q = 0; q < 6; q++) {
            const int i = tid + q * 256;
            if (i < CH * XPROJ_N) xd_s[i] = g_xdbl[bl0 * XPROJ_N + i];
        }
        __syncthreads();
        // phase 2: dt = softplus(xd.W_dt + b); wu = dt*u; accD += gate*u;
        // plus Bp/Cp transpose into [n][li] layout.
#pragma unroll
        for (int q = 0; q < 2; q++) {
            const int li = p_li + q * 16;
            float dtr = bdt_s[p_dd];
#pragma unroll
            for (int r = 0; r < DT_RANK; r++)
                dtr = fmaf(xd_s[li * XPROJ_N + r], Wdt_s[r][p_dd], dtr);
            const float w = (dtr > 15.0f) ? dtr : log1pf(__expf(dtr));
            const float u = wu_s[p_dd][li];
            const float gate = g_s[p_dd][li];
            w_s[p_dd][li]  = w;
            wu_s[p_dd][li] = w * u;
            accD_th = fmaf(gate, u, accD_th);
            bp_s[p_dd][li] = xd_s[li * XPROJ_N + DT_RANK + p_dd];
            cp_s[p_dd][li] = xd_s[li * XPROJ_N + DT_RANK + D_STATE + p_dd];
        }
        __syncthreads();
        // phase 3: serial scan over the chunk (all LDS.128)
#pragma unroll
        for (int l4 = 0; l4 < CH; l4 += 4) {
            const float4 w4  = *(const float4*)&w_s[gi][l4];
            const float4 wu4 = *(const float4*)&wu_s[gi][l4];
            const float4 g4  = *(const float4*)&g_s[gi][l4];
            const float4 bp4 = *(const float4*)&bp_s[n][l4];
            const float4 cp4 = *(const float4*)&cp_s[n][l4];
#pragma unroll
            for (int q = 0; q < 4; q++) {
                const float w  = (q == 0) ? w4.x  : (q == 1) ? w4.y  : (q == 2) ? w4.z  : w4.w;
                const float wu = (q == 0) ? wu4.x : (q == 1) ? wu4.y : (q == 2) ? wu4.z : wu4.w;
                const float gt = (q == 0) ? g4.x  : (q == 1) ? g4.y  : (q == 2) ? g4.z  : g4.w;
                const float bn = (q == 0) ? bp4.x : (q == 1) ? bp4.y : (q == 2) ? bp4.z : bp4.w;
                const float cn = (q == 0) ? cp4.x : (q == 1) ? cp4.y : (q == 2) ? cp4.z : cp4.w;
                const float dA = __expf(w * A_n);
                P *= dA;
                h = fmaf(dA, h, wu * bn);
                const float gc = gt * cn;
                acc  = fmaf(gc, h, acc);
                coef = fmaf(gc, P, coef);
            }
        }
    }
    // write packed segment summary (coalesced: tid -> consecutive [d][n])
    const size_t base = ((size_t)(b * SEGS + s) * D_INNER + d0) * D_STATE + tid;
    g_seg[base] = make_float4(acc, coef, P, h);
    // accD reduction over the 16 li-threads per dd
    accD_red[p_li][p_dd] = accD_th;
    __syncthreads();
    if (n == 0) {
        float accD = 0.f;
#pragma unroll
        for (int g = 0; g < 16; g++) accD += accD_red[g][gi];
        g_accD[(size_t)(b * SEGS + s) * D_INNER + d] = accD;
    }
}

// ---------------------------------------------------------------------------
// K5: fixup — combine SEGS segment summaries per chain, reduce over n,
// apply D-skip, write pooled mean.
// ---------------------------------------------------------------------------
__global__ __launch_bounds__(256) void scan_fix_kernel(const float* __restrict__ Dp) {
    const int idx = blockIdx.x * 256 + threadIdx.x;     // over 4*512*16
    const int n = idx & 15;
    const int d = (idx >> 4) & (D_INNER - 1);
    const int b = idx >> 13;

    float carry = 0.f, accT = 0.f, accD = 0.f;
#pragma unroll
    for (int s = 0; s < SEGS; s++) {
        const float4 sg = g_seg[((size_t)(b * SEGS + s) * D_INNER + d) * D_STATE + n];
        accT  = accT + sg.x + sg.y * carry;      // locAcc + coef*carry
        carry = fmaf(sg.z, carry, sg.w);         // Aprod*carry + hend
        if (n == 0) accD += g_accD[(size_t)(b * SEGS + s) * D_INNER + d];
    }
#pragma unroll
    for (int off = 8; off >= 1; off >>= 1)
        accT += __shfl_xor_sync(0xffffffffu, accT, off);
    if (n == 0)
        g_pooled[b * D_INNER + d] = (accT + Dp[d] * accD) * (1.0f / SEQ_LEN);
}

// ---------------------------------------------------------------------------
// K6: logits = (pooled @ W_out) @ W_cls + b_cls   (tiny)
// ---------------------------------------------------------------------------
__global__ __launch_bounds__(256) void final_kernel(const float* __restrict__ W_out,
                                                    const float* __restrict__ W_cls,
                                                    const float* __restrict__ b_cls,
                                                    float* __restrict__ out) {
    __shared__ float p_s[B_SZ * D_INNER];
    __shared__ float t_s[B_SZ * D_MODEL];
    const int tid = threadIdx.x;
    for (int i = tid; i < B_SZ * D_INNER; i += 256) p_s[i] = g_pooled[i];
    __syncthreads();
    float a0 = 0.f, a1 = 0.f, a2 = 0.f, a3 = 0.f;
    for (int k = 0; k < D_INNER; k++) {
        const float w = W_out[k * D_MODEL + tid];
        a0 = fmaf(p_s[k], w, a0);
        a1 = fmaf(p_s[D_INNER + k], w, a1);
        a2 = fmaf(p_s[2 * D_INNER + k], w, a2);
        a3 = fmaf(p_s[3 * D_INNER + k], w, a3);
    }
    t_s[tid] = a0; t_s[D_MODEL + tid] = a1;
    t_s[2 * D_MODEL + tid] = a2; t_s[3 * D_MODEL + tid] = a3;
    __syncthreads();
    if (tid < B_SZ * N_CLS) {
        const int bb = tid / N_CLS, c = tid % N_CLS;
        float acc = b_cls[c];
        for (int k = 0; k < D_MODEL; k++)
            acc = fmaf(t_s[bb * D_MODEL + k], W_cls[k * N_CLS + c], acc);
        out[tid] = acc;
    }
}

// ---------------------------------------------------------------------------
extern "C" void kernel_launch(void* const* d_in, const int* in_sizes, int n_in,
                              void* d_out, int out_size) {
    const float* x       = (const float*)d_in[0];
    const float* W_in    = (const float*)d_in[1];
    const float* W_conv  = (const float*)d_in[2];
    const float* b_conv  = (const float*)d_in[3];
    const float* W_xproj = (const float*)d_in[4];
    const float* W_dt    = (const float*)d_in[5];
    const float* b_dt    = (const float*)d_in[6];
    const float* A_log   = (const float*)d_in[7];
    const float* Dp      = (const float*)d_in[8];
    const float* W_out   = (const float*)d_in[9];
    const float* W_cls   = (const float*)d_in[10];
    const float* b_cls   = (const float*)d_in[11];
    float* out = (float*)d_out;

    gemm1_tc_kernel<<<dim3(2 * D_INNER / 128, BL / 128), 256>>>(x, W_in);
    conv_kernel<<<BL * D_INNER / 256, 256>>>(W_conv, b_conv);
    xproj_tc_kernel<<<BL / 64, 256>>>(W_xproj);
    scan_seg_kernel<<<B_SZ * SEGS * (D_INNER / 16), 256>>>(A_log, W_dt, b_dt);
    scan_fix_kernel<<<B_SZ * D_INNER * D_STATE / 256, 256>>>(Dp);
    final_kernel<<<1, 256>>>(W_out, W_cls, b_cls, out);
}